// round 2
// baseline (speedup 1.0000x reference)
#include <cuda_runtime.h>
#include <cuda_bf16.h>
#include <math.h>

// Problem shapes (compile-time)
#define B_   2
#define L_   1024
#define Mrows (B_*L_)      // 2048
#define DM   1024
#define DS   16
#define DFF  4096
#define DI   2048          // 2*DM
#define DTR  64            // ceil(DM/16)
#define NXD  (DTR + 2*DS)  // 96
#define KCONV 4

// ---------------------------------------------------------------------------
// Scratch buffers (device globals; no runtime allocation allowed)
// ---------------------------------------------------------------------------
__device__ float g_xz   [(size_t)Mrows * (2*DI)];   // 2048 x 4096
__device__ float g_xconv[(size_t)Mrows * DI];       // 2048 x 2048
__device__ float g_xdbl [(size_t)Mrows * NXD];      // 2048 x 96
__device__ float g_dt   [(size_t)Mrows * DI];       // 2048 x 2048
__device__ float g_y    [(size_t)Mrows * DI];       // 2048 x 2048
__device__ float g_ymam [(size_t)Mrows * DM];       // 2048 x 1024
__device__ float g_zm   [(size_t)Mrows * DM];       // 2048 x 1024
__device__ float g_h    [(size_t)Mrows * DFF];      // 2048 x 4096
__device__ float g_mlp  [(size_t)Mrows * DM];       // 2048 x 1024

// ---------------------------------------------------------------------------
// Generic NT GEMM:  C[m,n] = sum_k A[m,k] * W[n,k]   (both K-contiguous)
// EPI: 0=none, 1=softplus(acc+bias), 2=gelu(acc+bias), 3=acc+bias
// ---------------------------------------------------------------------------
template<int BM, int BN, int BK, int TM, int TN, int EPI>
__global__ void __launch_bounds__((BM/TM)*(BN/TN))
gemm_nt(const float* __restrict__ A, int lda,
        const float* __restrict__ W, int ldw,
        float* __restrict__ C, int ldc, int K,
        const float* __restrict__ bias)
{
    constexpr int NT = (BM/TM)*(BN/TN);
    __shared__ float As[BK][BM + 4];
    __shared__ float Ws[BK][BN + 4];

    const int tid = threadIdx.x;
    const int m0  = blockIdx.y * BM;
    const int n0  = blockIdx.x * BN;
    const int tr  = tid / (BN/TN);
    const int tc  = tid % (BN/TN);

    float acc[TM][TN];
#pragma unroll
    for (int i = 0; i < TM; i++)
#pragma unroll
        for (int j = 0; j < TN; j++) acc[i][j] = 0.f;

    for (int k0 = 0; k0 < K; k0 += BK) {
        // Load A tile (BM x BK), store transposed
        for (int i = tid; i < BM*BK/4; i += NT) {
            int row = i / (BK/4);
            int q   = i % (BK/4);
            float4 v = *(const float4*)&A[(size_t)(m0+row)*lda + k0 + q*4];
            As[q*4+0][row] = v.x; As[q*4+1][row] = v.y;
            As[q*4+2][row] = v.z; As[q*4+3][row] = v.w;
        }
        // Load W tile (BN x BK), store transposed
        for (int i = tid; i < BN*BK/4; i += NT) {
            int row = i / (BK/4);
            int q   = i % (BK/4);
            float4 v = *(const float4*)&W[(size_t)(n0+row)*ldw + k0 + q*4];
            Ws[q*4+0][row] = v.x; Ws[q*4+1][row] = v.y;
            Ws[q*4+2][row] = v.z; Ws[q*4+3][row] = v.w;
        }
        __syncthreads();

#pragma unroll
        for (int k = 0; k < BK; k++) {
            float a[TM], b[TN];
#pragma unroll
            for (int i = 0; i < TM; i++) a[i] = As[k][tr*TM + i];
#pragma unroll
            for (int j = 0; j < TN; j++) b[j] = Ws[k][tc*TN + j];
#pragma unroll
            for (int i = 0; i < TM; i++)
#pragma unroll
                for (int j = 0; j < TN; j++) acc[i][j] = fmaf(a[i], b[j], acc[i][j]);
        }
        __syncthreads();
    }

#pragma unroll
    for (int i = 0; i < TM; i++) {
        int m = m0 + tr*TM + i;
#pragma unroll
        for (int j = 0; j < TN; j++) {
            int n = n0 + tc*TN + j;
            float v = acc[i][j];
            if (EPI == 1) { // softplus
                v += bias[n];
                v = fmaxf(v, 0.f) + log1pf(__expf(-fabsf(v)));
            } else if (EPI == 2) { // exact gelu
                v += bias[n];
                v = 0.5f * v * (1.f + erff(v * 0.70710678118654752f));
            } else if (EPI == 3) {
                v += bias[n];
            }
            C[(size_t)m*ldc + n] = v;
        }
    }
}

// ---------------------------------------------------------------------------
// Causal depthwise conv (K=4) + SiLU over x half of xz
// ---------------------------------------------------------------------------
__global__ void conv_silu_kernel(const float* __restrict__ conv_w,
                                 const float* __restrict__ conv_b)
{
    int idx = blockIdx.x * blockDim.x + threadIdx.x;   // over Mrows*DI
    if (idx >= Mrows*DI) return;
    int d = idx & (DI-1);
    int m = idx >> 11;       // /DI
    int l = m & (L_-1);
    int mb = m - l;          // batch base row

    float acc = conv_b[d];
#pragma unroll
    for (int j = 0; j < KCONV; j++) {
        int ll = l - (KCONV-1) + j;
        if (ll >= 0)
            acc += g_xz[(size_t)(mb+ll)*(2*DI) + d] * conv_w[d*KCONV + j];
    }
    float s = 1.f / (1.f + __expf(-acc));
    g_xconv[idx] = acc * s;
}

// ---------------------------------------------------------------------------
// Selective scan: one thread per (batch, channel). h[16] in registers.
// y = (sum_n h[n]*C[n] + x*D) * silu(z)
// ---------------------------------------------------------------------------
__global__ void scan_kernel(const float* __restrict__ A_log,
                            const float* __restrict__ Dvec)
{
    int c = blockIdx.x * blockDim.x + threadIdx.x;     // 0..B_*DI-1
    int d = c & (DI-1);
    int b = c >> 11;

    float a[DS];
#pragma unroll
    for (int n = 0; n < DS; n++) a[n] = -__expf(A_log[d*DS + n]);
    float Dd = Dvec[d];

    float h[DS];
#pragma unroll
    for (int n = 0; n < DS; n++) h[n] = 0.f;

    int mbase = b * L_;
    for (int t = 0; t < L_; t++) {
        int m = mbase + t;
        float dtv = g_dt   [(size_t)m*DI + d];
        float xv  = g_xconv[(size_t)m*DI + d];
        float zv  = g_xz   [(size_t)m*(2*DI) + DI + d];
        const float* row = &g_xdbl[(size_t)m*NXD];

        float accy = 0.f;
        float dBase = dtv * xv;
#pragma unroll
        for (int n = 0; n < DS; n++) {
            float dA = __expf(dtv * a[n]);
            h[n] = fmaf(dA, h[n], dBase * row[DTR + n]);
            accy = fmaf(h[n], row[DTR + DS + n], accy);
        }
        float sg = 1.f / (1.f + __expf(-zv));
        g_y[(size_t)m*DI + d] = (accy + xv*Dd) * (zv * sg);
    }
}

// ---------------------------------------------------------------------------
// out = rmsnorm(a + b) * w    (row length DM=1024, 256 threads/row, 4 elems ea)
// ---------------------------------------------------------------------------
__global__ void addnorm_kernel(const float* __restrict__ a,
                               const float* __restrict__ b,
                               const float* __restrict__ w,
                               float* __restrict__ out)
{
    __shared__ float red[8];
    __shared__ float rshared;
    int m = blockIdx.x;
    int tid = threadIdx.x;      // 256

    float4 va = *(const float4*)&a[(size_t)m*DM + tid*4];
    float4 vb = *(const float4*)&b[(size_t)m*DM + tid*4];
    float v0 = va.x + vb.x, v1 = va.y + vb.y, v2 = va.z + vb.z, v3 = va.w + vb.w;
    float ss = v0*v0 + v1*v1 + v2*v2 + v3*v3;
#pragma unroll
    for (int o = 16; o; o >>= 1) ss += __shfl_xor_sync(0xFFFFFFFFu, ss, o);
    if ((tid & 31) == 0) red[tid >> 5] = ss;
    __syncthreads();
    if (tid == 0) {
        float s = 0.f;
#pragma unroll
        for (int i = 0; i < 8; i++) s += red[i];
        rshared = rsqrtf(s * (1.f/DM) + 1e-6f);
    }
    __syncthreads();
    float r = rshared;
    float4 vw = *(const float4*)&w[tid*4];
    float4 o4 = make_float4(v0*r*vw.x, v1*r*vw.y, v2*r*vw.z, v3*r*vw.w);
    *(float4*)&out[(size_t)m*DM + tid*4] = o4;
}

// ---------------------------------------------------------------------------
// Launch
// ---------------------------------------------------------------------------
static float* sym_addr(const void* sym) {
    void* p = nullptr;
    cudaGetSymbolAddress(&p, sym);
    return (float*)p;
}

extern "C" void kernel_launch(void* const* d_in, const int* in_sizes, int n_in,
                              void* d_out, int out_size)
{
    const float* Z     = (const float*)d_in[0];
    const float* ipw   = (const float*)d_in[1];   // (2*DI, DM)
    const float* convw = (const float*)d_in[2];   // (DI, 4)
    const float* convb = (const float*)d_in[3];   // (DI)
    const float* xpw   = (const float*)d_in[4];   // (96, DI)
    const float* dtw   = (const float*)d_in[5];   // (DI, 64)
    const float* dtb   = (const float*)d_in[6];   // (DI)
    const float* A_log = (const float*)d_in[7];   // (DI, 16)
    const float* Dvec  = (const float*)d_in[8];   // (DI)
    const float* opw   = (const float*)d_in[9];   // (DM, DI)
    const float* w1    = (const float*)d_in[10];  // (DFF, DM)
    const float* b1    = (const float*)d_in[11];  // (DFF)
    const float* w2    = (const float*)d_in[12];  // (DM, DFF)
    const float* b2    = (const float*)d_in[13];  // (DM)
    const float* nw    = (const float*)d_in[14];  // (DM)
    float* out = (float*)d_out;

    float* xz    = sym_addr(g_xz);
    float* xconv = sym_addr(g_xconv);
    float* xdbl  = sym_addr(g_xdbl);
    float* dt    = sym_addr(g_dt);
    float* y     = sym_addr(g_y);
    float* ymam  = sym_addr(g_ymam);
    float* zm    = sym_addr(g_zm);
    float* h     = sym_addr(g_h);
    float* mlp   = sym_addr(g_mlp);

    // 1) xz = Z @ in_proj_w^T           (2048 x 4096, K=1024)
    gemm_nt<128,128,8,8,8,0><<<dim3((2*DI)/128, Mrows/128), 256>>>(
        Z, DM, ipw, DM, xz, 2*DI, DM, nullptr);

    // 2) causal depthwise conv + silu -> xconv (2048 x 2048)
    conv_silu_kernel<<<(Mrows*DI)/256, 256>>>(convw, convb);

    // 3) xdbl = xconv @ x_proj_w^T      (2048 x 96, K=2048)
    gemm_nt<64,32,16,4,2,0><<<dim3(NXD/32, Mrows/64), 256>>>(
        xconv, DI, xpw, DI, xdbl, NXD, DI, nullptr);

    // 4) dt = softplus(xdbl[:, :64] @ dt_proj_w^T + dt_b)   (2048 x 2048, K=64)
    gemm_nt<128,128,8,8,8,1><<<dim3(DI/128, Mrows/128), 256>>>(
        xdbl, NXD, dtw, DTR, dt, DI, DTR, dtb);

    // 5) selective scan -> y (2048 x 2048)
    scan_kernel<<<(B_*DI)/128, 128>>>(A_log, Dvec);

    // 6) ymam = y @ out_proj_w^T        (2048 x 1024, K=2048)
    gemm_nt<128,128,8,8,8,0><<<dim3(DM/128, Mrows/128), 256>>>(
        y, DI, opw, DI, ymam, DM, DI, nullptr);

    // 7) zm = rmsnorm(ymam + Z) * nw
    addnorm_kernel<<<Mrows, 256>>>(ymam, Z, nw, zm);

    // 8) h = gelu(zm @ mlp_w1^T + b1)   (2048 x 4096, K=1024)
    gemm_nt<128,128,8,8,8,2><<<dim3(DFF/128, Mrows/128), 256>>>(
        zm, DM, w1, DM, h, DFF, DM, b1);

    // 9) mlp = h @ mlp_w2^T + b2        (2048 x 1024, K=4096)
    gemm_nt<128,128,8,8,8,3><<<dim3(DM/128, Mrows/128), 256>>>(
        h, DFF, w2, DFF, mlp, DM, DFF, b2);

    // 10) out = rmsnorm(mlp + zm) * nw
    addnorm_kernel<<<Mrows, 256>>>(mlp, zm, nw, out);
}

// round 7
// speedup vs baseline: 2.0767x; 2.0767x over previous
#include <cuda_runtime.h>
#include <cuda_bf16.h>
#include <stdint.h>
#include <stddef.h>
#include <math.h>

// Problem shapes (compile-time)
#define B_   2
#define L_   1024
#define Mrows (B_*L_)      // 2048
#define DM   1024
#define DS   16
#define DFF  4096
#define DI   2048          // 2*DM
#define DTR  64            // ceil(DM/16)
#define NXD  (DTR + 2*DS)  // 96
#define KCONV 4

// ---------------------------------------------------------------------------
// Scratch buffers (device globals; no runtime allocation allowed)
// ---------------------------------------------------------------------------
__device__ float g_xz   [(size_t)Mrows * (2*DI)];   // 2048 x 4096
__device__ float g_xconv[(size_t)Mrows * DI];       // 2048 x 2048
__device__ float g_xdbl [(size_t)Mrows * NXD];      // 2048 x 96
__device__ float g_dt   [(size_t)Mrows * DI];       // 2048 x 2048
__device__ float g_y    [(size_t)Mrows * DI];       // 2048 x 2048
__device__ float g_ymam [(size_t)Mrows * DM];       // 2048 x 1024
__device__ float g_zm   [(size_t)Mrows * DM];       // 2048 x 1024
__device__ float g_h    [(size_t)Mrows * DFF];      // 2048 x 4096
__device__ float g_mlp  [(size_t)Mrows * DM];       // 2048 x 1024

// ---------------------------------------------------------------------------
// TF32 helpers
// ---------------------------------------------------------------------------
__device__ __forceinline__ float tf32r(float x) {
    uint32_t u;
    asm("cvt.rna.tf32.f32 %0, %1;" : "=r"(u) : "f"(x));
    return __uint_as_float(u);
}

__device__ __forceinline__ void mma_tf32(float* c, float2 a02, float2 a13, float2 b) {
    uint32_t a0 = __float_as_uint(a02.x), a1 = __float_as_uint(a13.x);
    uint32_t a2 = __float_as_uint(a02.y), a3 = __float_as_uint(a13.y);
    uint32_t b0 = __float_as_uint(b.x),  b1 = __float_as_uint(b.y);
    asm volatile(
        "mma.sync.aligned.m16n8k8.row.col.f32.tf32.tf32.f32 "
        "{%0,%1,%2,%3},{%4,%5,%6,%7},{%8,%9},{%0,%1,%2,%3};"
        : "+f"(c[0]), "+f"(c[1]), "+f"(c[2]), "+f"(c[3])
        : "r"(a0), "r"(a1), "r"(a2), "r"(a3), "r"(b0), "r"(b1));
}

// ---------------------------------------------------------------------------
// TF32 tensor-core NT GEMM: C[m,n] = sum_k A[m,k] * W[n,k]
// BM=BN=128, BK=16. 8 warps in 2x4 grid, warp tile 64x32 (4 mtiles x 4 ntiles).
// Smem pair-layout: As[m][(o*4+p)*2+hi] = tf32(A[m][o*8+p+4*hi]) so each
// m16n8k8 fragment is a single LDS.64.
// EPI: 0=none, 1=softplus(+bias), 2=gelu(+bias), 3=+bias
// ---------------------------------------------------------------------------
template<int EPI>
__global__ void __launch_bounds__(256)
gemm_tf32(const float* __restrict__ A, int lda,
          const float* __restrict__ W, int ldw,
          float* __restrict__ C, int ldc, int K,
          const float* __restrict__ bias)
{
    __shared__ float As[128][18];
    __shared__ float Ws[128][18];

    const int tid  = threadIdx.x;
    const int warp = tid >> 5, lane = tid & 31;
    const int wm = warp >> 2, wn = warp & 3;      // 2 x 4 warp grid
    const int gid = lane >> 2, tig = lane & 3;
    const int m0 = blockIdx.y * 128, n0 = blockIdx.x * 128;
    const int r = tid >> 2, q = tid & 3;          // rows r and r+64, k-quad q

    float acc[4][4][4];
#pragma unroll
    for (int i = 0; i < 4; i++)
#pragma unroll
        for (int j = 0; j < 4; j++)
#pragma unroll
            for (int e = 0; e < 4; e++) acc[i][j][e] = 0.f;

    float4 ra0, ra1, rw0, rw1;

    // prefetch first tile
    {
        ra0 = *(const float4*)&A[(size_t)(m0 + r     )*lda + q*4];
        ra1 = *(const float4*)&A[(size_t)(m0 + r + 64)*lda + q*4];
        rw0 = *(const float4*)&W[(size_t)(n0 + r     )*ldw + q*4];
        rw1 = *(const float4*)&W[(size_t)(n0 + r + 64)*ldw + q*4];
    }

    const int colbase = (q >> 1)*8 + (q & 1);   // + c*2 per element

    for (int k0 = 0; k0 < K; k0 += 16) {
        // stage prefetched regs -> smem (with tf32 conversion)
        {
            float va0[4] = {ra0.x, ra0.y, ra0.z, ra0.w};
            float va1[4] = {ra1.x, ra1.y, ra1.z, ra1.w};
            float vw0[4] = {rw0.x, rw0.y, rw0.z, rw0.w};
            float vw1[4] = {rw1.x, rw1.y, rw1.z, rw1.w};
#pragma unroll
            for (int c = 0; c < 4; c++) {
                int col = colbase + c*2;
                As[r     ][col] = tf32r(va0[c]);
                As[r + 64][col] = tf32r(va1[c]);
                Ws[r     ][col] = tf32r(vw0[c]);
                Ws[r + 64][col] = tf32r(vw1[c]);
            }
        }
        __syncthreads();

        // prefetch next tile (overlaps with compute below)
        if (k0 + 16 < K) {
            int kn = k0 + 16;
            ra0 = *(const float4*)&A[(size_t)(m0 + r     )*lda + kn + q*4];
            ra1 = *(const float4*)&A[(size_t)(m0 + r + 64)*lda + kn + q*4];
            rw0 = *(const float4*)&W[(size_t)(n0 + r     )*ldw + kn + q*4];
            rw1 = *(const float4*)&W[(size_t)(n0 + r + 64)*ldw + kn + q*4];
        }

        // compute: 2 k-octets x 16 mma
#pragma unroll
        for (int o = 0; o < 2; o++) {
            float2 afr[4][2];
            float2 bfr[4];
            const int fcol = (o*4 + tig)*2;
#pragma unroll
            for (int mt = 0; mt < 4; mt++) {
                int m = wm*64 + mt*16 + gid;
                afr[mt][0] = *(const float2*)&As[m    ][fcol];
                afr[mt][1] = *(const float2*)&As[m + 8][fcol];
            }
#pragma unroll
            for (int nt = 0; nt < 4; nt++) {
                int n = wn*32 + nt*8 + gid;
                bfr[nt] = *(const float2*)&Ws[n][fcol];
            }
#pragma unroll
            for (int mt = 0; mt < 4; mt++)
#pragma unroll
                for (int nt = 0; nt < 4; nt++)
                    mma_tf32(acc[mt][nt], afr[mt][0], afr[mt][1], bfr[nt]);
        }
        __syncthreads();
    }

    // epilogue
#pragma unroll
    for (int mt = 0; mt < 4; mt++) {
        int row0 = m0 + wm*64 + mt*16 + gid;
        int row1 = row0 + 8;
#pragma unroll
        for (int nt = 0; nt < 4; nt++) {
            int col = n0 + wn*32 + nt*8 + tig*2;
            float v[4] = {acc[mt][nt][0], acc[mt][nt][1],
                          acc[mt][nt][2], acc[mt][nt][3]};
            if (EPI != 0) {
                float b0 = bias[col], b1 = bias[col+1];
                v[0] += b0; v[1] += b1; v[2] += b0; v[3] += b1;
#pragma unroll
                for (int e = 0; e < 4; e++) {
                    if (EPI == 1)       // softplus
                        v[e] = fmaxf(v[e], 0.f) + log1pf(__expf(-fabsf(v[e])));
                    else if (EPI == 2)  // exact gelu
                        v[e] = 0.5f * v[e] * (1.f + erff(v[e] * 0.70710678118654752f));
                }
            }
            *(float2*)&C[(size_t)row0*ldc + col] = make_float2(v[0], v[1]);
            *(float2*)&C[(size_t)row1*ldc + col] = make_float2(v[2], v[3]);
        }
    }
}

// ---------------------------------------------------------------------------
// SIMT NT GEMM (kept for the small N=96 x_proj GEMM)
// ---------------------------------------------------------------------------
template<int BM, int BN, int BK, int TM, int TN>
__global__ void __launch_bounds__((BM/TM)*(BN/TN))
gemm_nt(const float* __restrict__ A, int lda,
        const float* __restrict__ W, int ldw,
        float* __restrict__ C, int ldc, int K)
{
    constexpr int NT = (BM/TM)*(BN/TN);
    __shared__ float As[BK][BM + 4];
    __shared__ float Ws[BK][BN + 4];

    const int tid = threadIdx.x;
    const int m0  = blockIdx.y * BM;
    const int n0  = blockIdx.x * BN;
    const int tr  = tid / (BN/TN);
    const int tc  = tid % (BN/TN);

    float acc[TM][TN];
#pragma unroll
    for (int i = 0; i < TM; i++)
#pragma unroll
        for (int j = 0; j < TN; j++) acc[i][j] = 0.f;

    for (int k0 = 0; k0 < K; k0 += BK) {
        for (int i = tid; i < BM*BK/4; i += NT) {
            int row = i / (BK/4);
            int qq  = i % (BK/4);
            float4 v = *(const float4*)&A[(size_t)(m0+row)*lda + k0 + qq*4];
            As[qq*4+0][row] = v.x; As[qq*4+1][row] = v.y;
            As[qq*4+2][row] = v.z; As[qq*4+3][row] = v.w;
        }
        for (int i = tid; i < BN*BK/4; i += NT) {
            int row = i / (BK/4);
            int qq  = i % (BK/4);
            float4 v = *(const float4*)&W[(size_t)(n0+row)*ldw + k0 + qq*4];
            Ws[qq*4+0][row] = v.x; Ws[qq*4+1][row] = v.y;
            Ws[qq*4+2][row] = v.z; Ws[qq*4+3][row] = v.w;
        }
        __syncthreads();

#pragma unroll
        for (int k = 0; k < BK; k++) {
            float a[TM], b[TN];
#pragma unroll
            for (int i = 0; i < TM; i++) a[i] = As[k][tr*TM + i];
#pragma unroll
            for (int j = 0; j < TN; j++) b[j] = Ws[k][tc*TN + j];
#pragma unroll
            for (int i = 0; i < TM; i++)
#pragma unroll
                for (int j = 0; j < TN; j++) acc[i][j] = fmaf(a[i], b[j], acc[i][j]);
        }
        __syncthreads();
    }

#pragma unroll
    for (int i = 0; i < TM; i++) {
        int m = m0 + tr*TM + i;
#pragma unroll
        for (int j = 0; j < TN; j++) {
            int n = n0 + tc*TN + j;
            C[(size_t)m*ldc + n] = acc[i][j];
        }
    }
}

// ---------------------------------------------------------------------------
// Causal depthwise conv (K=4) + SiLU over x half of xz
// ---------------------------------------------------------------------------
__global__ void conv_silu_kernel(const float* __restrict__ conv_w,
                                 const float* __restrict__ conv_b)
{
    int idx = blockIdx.x * blockDim.x + threadIdx.x;   // over Mrows*DI
    if (idx >= Mrows*DI) return;
    int d = idx & (DI-1);
    int m = idx >> 11;       // /DI
    int l = m & (L_-1);
    int mb = m - l;          // batch base row

    float acc = conv_b[d];
#pragma unroll
    for (int j = 0; j < KCONV; j++) {
        int ll = l - (KCONV-1) + j;
        if (ll >= 0)
            acc += g_xz[(size_t)(mb+ll)*(2*DI) + d] * conv_w[d*KCONV + j];
    }
    float s = 1.f / (1.f + __expf(-acc));
    g_xconv[idx] = acc * s;
}

// ---------------------------------------------------------------------------
// Selective scan: 4 threads per (batch, channel), 4 states each.
// y = (sum_n h[n]*C[n] + x*D) * silu(z)
// ---------------------------------------------------------------------------
__global__ void scan_kernel(const float* __restrict__ A_log,
                            const float* __restrict__ Dvec)
{
    int t   = blockIdx.x * blockDim.x + threadIdx.x;   // 0 .. 4*B_*DI-1
    int sub = t & 3;
    int c   = t >> 2;
    int d   = c & (DI-1);
    int b   = c >> 11;

    float a[4];
#pragma unroll
    for (int n = 0; n < 4; n++) a[n] = -__expf(A_log[d*DS + sub*4 + n]);
    float Dd = Dvec[d];

    float h[4] = {0.f, 0.f, 0.f, 0.f};

    int mbase = b * L_;
    for (int step = 0; step < L_; step++) {
        int m = mbase + step;
        float dtv = g_dt   [(size_t)m*DI + d];
        float xv  = g_xconv[(size_t)m*DI + d];
        const float* row = &g_xdbl[(size_t)m*NXD];

        float accy = 0.f;
        float dBase = dtv * xv;
#pragma unroll
        for (int n = 0; n < 4; n++) {
            float dA = __expf(dtv * a[n]);
            h[n] = fmaf(dA, h[n], dBase * row[DTR + sub*4 + n]);
            accy = fmaf(h[n], row[DTR + DS + sub*4 + n], accy);
        }
        accy += __shfl_xor_sync(0xFFFFFFFFu, accy, 1);
        accy += __shfl_xor_sync(0xFFFFFFFFu, accy, 2);
        if (sub == 0) {
            float zv = g_xz[(size_t)m*(2*DI) + DI + d];
            float sg = 1.f / (1.f + __expf(-zv));
            g_y[(size_t)m*DI + d] = (accy + xv*Dd) * (zv * sg);
        }
    }
}

// ---------------------------------------------------------------------------
// out = rmsnorm(a + b) * w    (row length DM=1024, 256 threads/row)
// ---------------------------------------------------------------------------
__global__ void addnorm_kernel(const float* __restrict__ a,
                               const float* __restrict__ b,
                               const float* __restrict__ w,
                               float* __restrict__ out)
{
    __shared__ float red[8];
    __shared__ float rshared;
    int m = blockIdx.x;
    int tid = threadIdx.x;      // 256

    float4 va = *(const float4*)&a[(size_t)m*DM + tid*4];
    float4 vb = *(const float4*)&b[(size_t)m*DM + tid*4];
    float v0 = va.x + vb.x, v1 = va.y + vb.y, v2 = va.z + vb.z, v3 = va.w + vb.w;
    float ss = v0*v0 + v1*v1 + v2*v2 + v3*v3;
#pragma unroll
    for (int o = 16; o; o >>= 1) ss += __shfl_xor_sync(0xFFFFFFFFu, ss, o);
    if ((tid & 31) == 0) red[tid >> 5] = ss;
    __syncthreads();
    if (tid == 0) {
        float s = 0.f;
#pragma unroll
        for (int i = 0; i < 8; i++) s += red[i];
        rshared = rsqrtf(s * (1.f/DM) + 1e-6f);
    }
    __syncthreads();
    float r = rshared;
    float4 vw = *(const float4*)&w[tid*4];
    float4 o4 = make_float4(v0*r*vw.x, v1*r*vw.y, v2*r*vw.z, v3*r*vw.w);
    *(float4*)&out[(size_t)m*DM + tid*4] = o4;
}

// ---------------------------------------------------------------------------
// Launch
// ---------------------------------------------------------------------------
static float* sym_addr(const void* sym) {
    void* p = nullptr;
    cudaGetSymbolAddress(&p, sym);
    return (float*)p;
}

extern "C" void kernel_launch(void* const* d_in, const int* in_sizes, int n_in,
                              void* d_out, int out_size)
{
    const float* Z     = (const float*)d_in[0];
    const float* ipw   = (const float*)d_in[1];   // (2*DI, DM)
    const float* convw = (const float*)d_in[2];   // (DI, 4)
    const float* convb = (const float*)d_in[3];   // (DI)
    const float* xpw   = (const float*)d_in[4];   // (96, DI)
    const float* dtw   = (const float*)d_in[5];   // (DI, 64)
    const float* dtb   = (const float*)d_in[6];   // (DI)
    const float* A_log = (const float*)d_in[7];   // (DI, 16)
    const float* Dvec  = (const float*)d_in[8];   // (DI)
    const float* opw   = (const float*)d_in[9];   // (DM, DI)
    const float* w1    = (const float*)d_in[10];  // (DFF, DM)
    const float* b1    = (const float*)d_in[11];  // (DFF)
    const float* w2    = (const float*)d_in[12];  // (DM, DFF)
    const float* b2    = (const float*)d_in[13];  // (DM)
    const float* nw    = (const float*)d_in[14];  // (DM)
    float* out = (float*)d_out;

    float* xz    = sym_addr(g_xz);
    float* xconv = sym_addr(g_xconv);
    float* xdbl  = sym_addr(g_xdbl);
    float* dt    = sym_addr(g_dt);
    float* y     = sym_addr(g_y);
    float* ymam  = sym_addr(g_ymam);
    float* zm    = sym_addr(g_zm);
    float* h     = sym_addr(g_h);
    float* mlp   = sym_addr(g_mlp);

    // 1) xz = Z @ in_proj_w^T           (2048 x 4096, K=1024)  [TF32]
    gemm_tf32<0><<<dim3((2*DI)/128, Mrows/128), 256>>>(
        Z, DM, ipw, DM, xz, 2*DI, DM, nullptr);

    // 2) causal depthwise conv + silu -> xconv (2048 x 2048)
    conv_silu_kernel<<<(Mrows*DI)/256, 256>>>(convw, convb);

    // 3) xdbl = xconv @ x_proj_w^T      (2048 x 96, K=2048)  [SIMT, small]
    gemm_nt<64,32,16,4,2><<<dim3(NXD/32, Mrows/64), 256>>>(
        xconv, DI, xpw, DI, xdbl, NXD, DI);

    // 4) dt = softplus(xdbl[:, :64] @ dt_proj_w^T + dt_b)   (2048 x 2048, K=64)  [TF32]
    gemm_tf32<1><<<dim3(DI/128, Mrows/128), 256>>>(
        xdbl, NXD, dtw, DTR, dt, DI, DTR, dtb);

    // 5) selective scan -> y (2048 x 2048)
    scan_kernel<<<(4*B_*DI)/128, 128>>>(A_log, Dvec);

    // 6) ymam = y @ out_proj_w^T        (2048 x 1024, K=2048)  [TF32]
    gemm_tf32<0><<<dim3(DM/128, Mrows/128), 256>>>(
        y, DI, opw, DI, ymam, DM, DI, nullptr);

    // 7) zm = rmsnorm(ymam + Z) * nw
    addnorm_kernel<<<Mrows, 256>>>(ymam, Z, nw, zm);

    // 8) h = gelu(zm @ mlp_w1^T + b1)   (2048 x 4096, K=1024)  [TF32]
    gemm_tf32<2><<<dim3(DFF/128, Mrows/128), 256>>>(
        zm, DM, w1, DM, h, DFF, DM, b1);

    // 9) mlp = h @ mlp_w2^T + b2        (2048 x 1024, K=4096)  [TF32]
    gemm_tf32<3><<<dim3(DM/128, Mrows/128), 256>>>(
        h, DFF, w2, DFF, mlp, DM, DFF, b2);

    // 10) out = rmsnorm(mlp + zm) * nw
    addnorm_kernel<<<Mrows, 256>>>(mlp, zm, nw, out);
}

// round 8
// speedup vs baseline: 2.2907x; 1.1030x over previous
#include <cuda_runtime.h>
#include <cuda_bf16.h>
#include <stdint.h>
#include <stddef.h>
#include <math.h>

// Problem shapes (compile-time)
#define B_   2
#define L_   1024
#define Mrows (B_*L_)      // 2048
#define DM   1024
#define DS   16
#define DFF  4096
#define DI   2048          // 2*DM
#define DTR  64            // ceil(DM/16)
#define NXD  (DTR + 2*DS)  // 96
#define KCONV 4

// ---------------------------------------------------------------------------
// Scratch buffers (device globals; no runtime allocation allowed)
// ---------------------------------------------------------------------------
__device__ float g_xz   [(size_t)Mrows * (2*DI)];   // 2048 x 4096
__device__ float g_xconv[(size_t)Mrows * DI];       // 2048 x 2048
__device__ float g_xdbl [(size_t)Mrows * NXD];      // 2048 x 96
__device__ float g_dt   [(size_t)Mrows * DI];       // 2048 x 2048
__device__ float g_y    [(size_t)Mrows * DI];       // 2048 x 2048
__device__ float g_ymam [(size_t)Mrows * DM];       // 2048 x 1024
__device__ float g_zm   [(size_t)Mrows * DM];       // 2048 x 1024
__device__ float g_h    [(size_t)Mrows * DFF];      // 2048 x 4096
__device__ float g_mlp  [(size_t)Mrows * DM];       // 2048 x 1024

// ---------------------------------------------------------------------------
// TF32 helpers
// ---------------------------------------------------------------------------
__device__ __forceinline__ float tf32r(float x) {
    uint32_t u;
    asm("cvt.rna.tf32.f32 %0, %1;" : "=r"(u) : "f"(x));
    return __uint_as_float(u);
}

__device__ __forceinline__ void mma_tf32(float* c, float2 a02, float2 a13, float2 b) {
    uint32_t a0 = __float_as_uint(a02.x), a1 = __float_as_uint(a13.x);
    uint32_t a2 = __float_as_uint(a02.y), a3 = __float_as_uint(a13.y);
    uint32_t b0 = __float_as_uint(b.x),  b1 = __float_as_uint(b.y);
    asm volatile(
        "mma.sync.aligned.m16n8k8.row.col.f32.tf32.tf32.f32 "
        "{%0,%1,%2,%3},{%4,%5,%6,%7},{%8,%9},{%0,%1,%2,%3};"
        : "+f"(c[0]), "+f"(c[1]), "+f"(c[2]), "+f"(c[3])
        : "r"(a0), "r"(a1), "r"(a2), "r"(a3), "r"(b0), "r"(b1));
}

// ---------------------------------------------------------------------------
// TF32 tensor-core NT GEMM: C[m,n] = sum_k A[m,k] * W[n,k]
//
// Block 128x128xK, BK=16, double-buffered smem, 4 warps in 2x2 grid with
// 64x64 warp tiles (4 mtiles x 8 ntiles of m16n8k8).
//
// Smem layout per tile row (16 cols, stride 16 floats):
//   logical col(k) = 4*(k%4) + 2*(k/8) + ((k/4)%2)   (k in 0..15)
//   physical col   = logical ^ (4*(row & 3))          (XOR swizzle)
// => a thread's A/B fragments for BOTH k-octets are ONE conflict-free LDS.128:
//    float4 at col 4*(tig ^ (row&3)) = (k=tig, k=tig+4, k=tig+8, k=tig+12).
//
// EPI: 0=none, 1=softplus(+bias), 2=gelu(+bias), 3=+bias
// NB : bound W rows / C cols by Nact (for N=96 x_proj GEMM)
// ---------------------------------------------------------------------------
template<int EPI, bool NB>
__global__ void __launch_bounds__(128, 2)
gemm_tf32(const float* __restrict__ A, int lda,
          const float* __restrict__ W, int ldw,
          float* __restrict__ C, int ldc, int K, int Nact,
          const float* __restrict__ bias)
{
    __shared__ __align__(16) float As[2][128][16];
    __shared__ __align__(16) float Ws[2][128][16];

    const int tid  = threadIdx.x;
    const int warp = tid >> 5, lane = tid & 31;
    const int wm = warp >> 1, wn = warp & 1;         // 2x2 warp grid
    const int gid = lane >> 2, tig = lane & 3;
    const int m0 = blockIdx.y * 128, n0 = blockIdx.x * 128;
    const int r = tid >> 2, q = tid & 3;             // staging: rows r+32p, k-quad q

    float acc[4][8][4];
#pragma unroll
    for (int i = 0; i < 4; i++)
#pragma unroll
        for (int j = 0; j < 8; j++)
#pragma unroll
            for (int e = 0; e < 4; e++) acc[i][j][e] = 0.f;

    // --- staging global pointers + swizzled smem column offsets (hoisted) ---
    const float* pA[4]; const float* pW[4]; bool wok[4];
#pragma unroll
    for (int p = 0; p < 4; p++) {
        pA[p] = A + (size_t)(m0 + r + 32*p)*lda + q*4;
        int wrow = n0 + r + 32*p;
        wok[p] = !NB || (wrow < Nact);
        pW[p] = W + (size_t)(wok[p] ? wrow : 0)*ldw + q*4;
    }
    int scol[4];
#pragma unroll
    for (int c = 0; c < 4; c++) scol[c] = q + 4*(c ^ (r & 3));

    // --- fragment smem offsets (hoisted; same for both buffers) ---
    int arow[4], acol[4], brow[8], bcol[8];
#pragma unroll
    for (int mt = 0; mt < 4; mt++) {
        arow[mt] = wm*64 + mt*16 + gid;
        acol[mt] = 4*(tig ^ (arow[mt] & 3));
    }
#pragma unroll
    for (int nt = 0; nt < 8; nt++) {
        brow[nt] = wn*64 + nt*8 + gid;
        bcol[nt] = 4*(tig ^ (brow[nt] & 3));
    }

    // --- prologue: load + stage tile 0 ---
    float4 ra[4], rw[4];
#pragma unroll
    for (int p = 0; p < 4; p++) {
        ra[p] = *(const float4*)pA[p];
        rw[p] = wok[p] ? *(const float4*)pW[p] : make_float4(0.f,0.f,0.f,0.f);
    }
#pragma unroll
    for (int p = 0; p < 4; p++) {
        int row = r + 32*p;
        float va[4] = {ra[p].x, ra[p].y, ra[p].z, ra[p].w};
        float vw[4] = {rw[p].x, rw[p].y, rw[p].z, rw[p].w};
#pragma unroll
        for (int c = 0; c < 4; c++) {
            As[0][row][scol[c]] = tf32r(va[c]);
            Ws[0][row][scol[c]] = tf32r(vw[c]);
        }
    }
    __syncthreads();

    const int T = K >> 4;
    for (int t = 0; t < T; t++) {
        const int cur = t & 1;
        const bool hn = (t + 1 < T);
        if (hn) {
#pragma unroll
            for (int p = 0; p < 4; p++) {
                pA[p] += 16; pW[p] += 16;
                ra[p] = *(const float4*)pA[p];
                rw[p] = wok[p] ? *(const float4*)pW[p] : make_float4(0.f,0.f,0.f,0.f);
            }
        }

        // fragments for both octets in one LDS.128 each
        float4 af[4][2], bf[8];
#pragma unroll
        for (int mt = 0; mt < 4; mt++) {
            af[mt][0] = *(const float4*)&As[cur][arow[mt]    ][acol[mt]];
            af[mt][1] = *(const float4*)&As[cur][arow[mt] + 8][acol[mt]];
        }
#pragma unroll
        for (int nt = 0; nt < 8; nt++)
            bf[nt] = *(const float4*)&Ws[cur][brow[nt]][bcol[nt]];

#pragma unroll
        for (int mt = 0; mt < 4; mt++)
#pragma unroll
            for (int nt = 0; nt < 8; nt++) {
                mma_tf32(acc[mt][nt],
                         make_float2(af[mt][0].x, af[mt][0].y),
                         make_float2(af[mt][1].x, af[mt][1].y),
                         make_float2(bf[nt].x, bf[nt].y));
                mma_tf32(acc[mt][nt],
                         make_float2(af[mt][0].z, af[mt][0].w),
                         make_float2(af[mt][1].z, af[mt][1].w),
                         make_float2(bf[nt].z, bf[nt].w));
            }

        if (hn) {
            const int nxt = cur ^ 1;
#pragma unroll
            for (int p = 0; p < 4; p++) {
                int row = r + 32*p;
                float va[4] = {ra[p].x, ra[p].y, ra[p].z, ra[p].w};
                float vw[4] = {rw[p].x, rw[p].y, rw[p].z, rw[p].w};
#pragma unroll
                for (int c = 0; c < 4; c++) {
                    As[nxt][row][scol[c]] = tf32r(va[c]);
                    Ws[nxt][row][scol[c]] = tf32r(vw[c]);
                }
            }
            __syncthreads();
        }
    }

    // --- epilogue ---
#pragma unroll
    for (int mt = 0; mt < 4; mt++) {
        int row0 = m0 + wm*64 + mt*16 + gid;
        int row1 = row0 + 8;
#pragma unroll
        for (int nt = 0; nt < 8; nt++) {
            int col = n0 + wn*64 + nt*8 + tig*2;
            if (NB && col >= Nact) continue;
            float v[4] = {acc[mt][nt][0], acc[mt][nt][1],
                          acc[mt][nt][2], acc[mt][nt][3]};
            if (EPI != 0) {
                float b0 = bias[col], b1 = bias[col+1];
                v[0] += b0; v[1] += b1; v[2] += b0; v[3] += b1;
#pragma unroll
                for (int e = 0; e < 4; e++) {
                    if (EPI == 1)       // softplus
                        v[e] = fmaxf(v[e], 0.f) + log1pf(__expf(-fabsf(v[e])));
                    else if (EPI == 2)  // exact gelu
                        v[e] = 0.5f * v[e] * (1.f + erff(v[e] * 0.70710678118654752f));
                }
            }
            *(float2*)&C[(size_t)row0*ldc + col] = make_float2(v[0], v[1]);
            *(float2*)&C[(size_t)row1*ldc + col] = make_float2(v[2], v[3]);
        }
    }
}

// ---------------------------------------------------------------------------
// Causal depthwise conv (K=4) + SiLU over x half of xz
// ---------------------------------------------------------------------------
__global__ void conv_silu_kernel(const float* __restrict__ conv_w,
                                 const float* __restrict__ conv_b)
{
    int idx = blockIdx.x * blockDim.x + threadIdx.x;   // over Mrows*DI
    if (idx >= Mrows*DI) return;
    int d = idx & (DI-1);
    int m = idx >> 11;       // /DI
    int l = m & (L_-1);
    int mb = m - l;          // batch base row

    float acc = conv_b[d];
#pragma unroll
    for (int j = 0; j < KCONV; j++) {
        int ll = l - (KCONV-1) + j;
        if (ll >= 0)
            acc += g_xz[(size_t)(mb+ll)*(2*DI) + d] * conv_w[d*KCONV + j];
    }
    float s = 1.f / (1.f + __expf(-acc));
    g_xconv[idx] = acc * s;
}

// ---------------------------------------------------------------------------
// Selective scan: 4 threads per (batch, channel), 4 states each.
// y = (sum_n h[n]*C[n] + x*D) * silu(z)
// ---------------------------------------------------------------------------
__global__ void scan_kernel(const float* __restrict__ A_log,
                            const float* __restrict__ Dvec)
{
    int t   = blockIdx.x * blockDim.x + threadIdx.x;   // 0 .. 4*B_*DI-1
    int sub = t & 3;
    int c   = t >> 2;
    int d   = c & (DI-1);
    int b   = c >> 11;

    float a[4];
#pragma unroll
    for (int n = 0; n < 4; n++) a[n] = -__expf(A_log[d*DS + sub*4 + n]);
    float Dd = Dvec[d];

    float h[4] = {0.f, 0.f, 0.f, 0.f};

    int mbase = b * L_;
    for (int step = 0; step < L_; step++) {
        int m = mbase + step;
        float dtv = g_dt   [(size_t)m*DI + d];
        float xv  = g_xconv[(size_t)m*DI + d];
        const float* row = &g_xdbl[(size_t)m*NXD];

        float accy = 0.f;
        float dBase = dtv * xv;
#pragma unroll
        for (int n = 0; n < 4; n++) {
            float dA = __expf(dtv * a[n]);
            h[n] = fmaf(dA, h[n], dBase * row[DTR + sub*4 + n]);
            accy = fmaf(h[n], row[DTR + DS + sub*4 + n], accy);
        }
        accy += __shfl_xor_sync(0xFFFFFFFFu, accy, 1);
        accy += __shfl_xor_sync(0xFFFFFFFFu, accy, 2);
        if (sub == 0) {
            float zv = g_xz[(size_t)m*(2*DI) + DI + d];
            float sg = 1.f / (1.f + __expf(-zv));
            g_y[(size_t)m*DI + d] = (accy + xv*Dd) * (zv * sg);
        }
    }
}

// ---------------------------------------------------------------------------
// out = rmsnorm(a + b) * w    (row length DM=1024, 256 threads/row)
// ---------------------------------------------------------------------------
__global__ void addnorm_kernel(const float* __restrict__ a,
                               const float* __restrict__ b,
                               const float* __restrict__ w,
                               float* __restrict__ out)
{
    __shared__ float red[8];
    __shared__ float rshared;
    int m = blockIdx.x;
    int tid = threadIdx.x;      // 256

    float4 va = *(const float4*)&a[(size_t)m*DM + tid*4];
    float4 vb = *(const float4*)&b[(size_t)m*DM + tid*4];
    float v0 = va.x + vb.x, v1 = va.y + vb.y, v2 = va.z + vb.z, v3 = va.w + vb.w;
    float ss = v0*v0 + v1*v1 + v2*v2 + v3*v3;
#pragma unroll
    for (int o = 16; o; o >>= 1) ss += __shfl_xor_sync(0xFFFFFFFFu, ss, o);
    if ((tid & 31) == 0) red[tid >> 5] = ss;
    __syncthreads();
    if (tid == 0) {
        float s = 0.f;
#pragma unroll
        for (int i = 0; i < 8; i++) s += red[i];
        rshared = rsqrtf(s * (1.f/DM) + 1e-6f);
    }
    __syncthreads();
    float r = rshared;
    float4 vw = *(const float4*)&w[tid*4];
    float4 o4 = make_float4(v0*r*vw.x, v1*r*vw.y, v2*r*vw.z, v3*r*vw.w);
    *(float4*)&out[(size_t)m*DM + tid*4] = o4;
}

// ---------------------------------------------------------------------------
// Launch
// ---------------------------------------------------------------------------
static float* sym_addr(const void* sym) {
    void* p = nullptr;
    cudaGetSymbolAddress(&p, sym);
    return (float*)p;
}

extern "C" void kernel_launch(void* const* d_in, const int* in_sizes, int n_in,
                              void* d_out, int out_size)
{
    const float* Z     = (const float*)d_in[0];
    const float* ipw   = (const float*)d_in[1];   // (2*DI, DM)
    const float* convw = (const float*)d_in[2];   // (DI, 4)
    const float* convb = (const float*)d_in[3];   // (DI)
    const float* xpw   = (const float*)d_in[4];   // (96, DI)
    const float* dtw   = (const float*)d_in[5];   // (DI, 64)
    const float* dtb   = (const float*)d_in[6];   // (DI)
    const float* A_log = (const float*)d_in[7];   // (DI, 16)
    const float* Dvec  = (const float*)d_in[8];   // (DI)
    const float* opw   = (const float*)d_in[9];   // (DM, DI)
    const float* w1    = (const float*)d_in[10];  // (DFF, DM)
    const float* b1    = (const float*)d_in[11];  // (DFF)
    const float* w2    = (const float*)d_in[12];  // (DM, DFF)
    const float* b2    = (const float*)d_in[13];  // (DM)
    const float* nw    = (const float*)d_in[14];  // (DM)
    float* out = (float*)d_out;

    float* xz    = sym_addr(g_xz);
    float* xconv = sym_addr(g_xconv);
    float* xdbl  = sym_addr(g_xdbl);
    float* dt    = sym_addr(g_dt);
    float* y     = sym_addr(g_y);
    float* ymam  = sym_addr(g_ymam);
    float* zm    = sym_addr(g_zm);
    float* h     = sym_addr(g_h);
    float* mlp   = sym_addr(g_mlp);

    // 1) xz = Z @ in_proj_w^T           (2048 x 4096, K=1024)  [TF32]
    gemm_tf32<0,false><<<dim3((2*DI)/128, Mrows/128), 128>>>(
        Z, DM, ipw, DM, xz, 2*DI, DM, 0, nullptr);

    // 2) causal depthwise conv + silu -> xconv (2048 x 2048)
    conv_silu_kernel<<<(Mrows*DI)/256, 256>>>(convw, convb);

    // 3) xdbl = xconv @ x_proj_w^T      (2048 x 96, K=2048)  [TF32, N-bounded]
    gemm_tf32<0,true><<<dim3(1, Mrows/128), 128>>>(
        xconv, DI, xpw, DI, xdbl, NXD, DI, NXD, nullptr);

    // 4) dt = softplus(xdbl[:, :64] @ dt_proj_w^T + dt_b)   (2048 x 2048, K=64)  [TF32]
    gemm_tf32<1,false><<<dim3(DI/128, Mrows/128), 128>>>(
        xdbl, NXD, dtw, DTR, dt, DI, DTR, 0, dtb);

    // 5) selective scan -> y (2048 x 2048)
    scan_kernel<<<(4*B_*DI)/128, 128>>>(A_log, Dvec);

    // 6) ymam = y @ out_proj_w^T        (2048 x 1024, K=2048)  [TF32]
    gemm_tf32<0,false><<<dim3(DM/128, Mrows/128), 128>>>(
        y, DI, opw, DI, ymam, DM, DI, 0, nullptr);

    // 7) zm = rmsnorm(ymam + Z) * nw
    addnorm_kernel<<<Mrows, 256>>>(ymam, Z, nw, zm);

    // 8) h = gelu(zm @ mlp_w1^T + b1)   (2048 x 4096, K=1024)  [TF32]
    gemm_tf32<2,false><<<dim3(DFF/128, Mrows/128), 128>>>(
        zm, DM, w1, DM, h, DFF, DM, 0, b1);

    // 9) mlp = h @ mlp_w2^T + b2        (2048 x 1024, K=4096)  [TF32]
    gemm_tf32<3,false><<<dim3(DM/128, Mrows/128), 128>>>(
        h, DFF, w2, DFF, mlp, DM, DFF, 0, b2);

    // 10) out = rmsnorm(mlp + zm) * nw
    addnorm_kernel<<<Mrows, 256>>>(mlp, zm, nw, out);
}